// round 9
// baseline (speedup 1.0000x reference)
#include <cuda_runtime.h>
#include <cuda_bf16.h>
#include <cstdint>

#define T_SEQ 2048
#define NBATCH 64
#define NIN 16
#define NHEAD 8
#define HID 64
#define NGATE 256

// h history scratch (device global; no runtime allocation)
__device__ float g_hist[(size_t)T_SEQ * NBATCH * NHEAD * HID];   // 256 MB

// ---- helpers ----
__device__ __forceinline__ uint32_t pack_bf16x2(__nv_bfloat16 a, __nv_bfloat16 b) {
    __nv_bfloat162 v; v.x = a; v.y = b;
    return *reinterpret_cast<uint32_t*>(&v);
}
__device__ __forceinline__ void split_bf16(float f, __nv_bfloat16& hi, __nv_bfloat16& lo) {
    hi = __float2bfloat16_rn(f);
    lo = __float2bfloat16_rn(f - __bfloat162float(hi));
}
__device__ __forceinline__ void mma16816(float& d0, float& d1, float& d2, float& d3,
                                         uint32_t a0, uint32_t a1, uint32_t a2, uint32_t a3,
                                         uint32_t b0, uint32_t b1) {
    asm volatile(
        "mma.sync.aligned.m16n8k16.row.col.f32.bf16.bf16.f32 "
        "{%0,%1,%2,%3},{%4,%5,%6,%7},{%8,%9},{%0,%1,%2,%3};"
        : "+f"(d0), "+f"(d1), "+f"(d2), "+f"(d3)
        : "r"(a0), "r"(a1), "r"(a2), "r"(a3), "r"(b0), "r"(b1));
}
__device__ __forceinline__ float tanha(float x) {
    float y; asm("tanh.approx.f32 %0, %1;" : "=f"(y) : "f"(x)); return y;
}
__device__ __forceinline__ float siga(float z) {
    return fmaf(0.5f, tanha(0.5f * z), 0.5f);
}
__device__ __forceinline__ uint32_t smem_u32(const void* p) {
    uint32_t a;
    asm("{ .reg .u64 t; cvta.to.shared.u64 t, %1; cvt.u32.u64 %0, t; }" : "=r"(a) : "l"(p));
    return a;
}

// ============================================================================
// Recurrent kernel: bf16 m16n8k16, gate-permuted tiles + register transpose,
// 2-CTA clusters with DSMEM h-exchange.
// Grid: 128 CTAs = 64 clusters (head x 8-batch group) x rank. Block: 256.
// CTA rank r owns cells j in [32r, 32r+32): 8 warps, each warp's m16 tile =
// 4 gates x 4 cells (permuted), 15 HMMA/step (3-term bf16 split, fp32 acc).
// h exchange: each thread stores h (bf16 hi/lo) to local AND peer smem
// (st.shared::cluster), arrives on both mbarriers; one wait per step
// (512 arrivals = 256 local + 256 remote).
// ============================================================================
__global__ __launch_bounds__(256, 1) __cluster_dims__(2, 1, 1)
void lstm_rec_mma(
    const float* __restrict__ x,     // (T,B,16)
    const float* __restrict__ W_ih,  // (8,256,16)
    const float* __restrict__ W_hh,  // (8,256,64)
    const float* __restrict__ b_ih,  // (8,256)
    const float* __restrict__ b_hh)  // (8,256)
{
    const int tid  = threadIdx.x;
    const int wid  = tid >> 5;        // 0..7
    const int lane = tid & 31;
    const int g    = lane >> 2;       // fragment group id (B: batch col)
    const int tg   = lane & 3;
    const int G    = g & 3;           // gate of this lane's A rows
    const int q    = g >> 2;          // j-slot base (0 or 1)

    uint32_t crank;
    asm("mov.u32 %0, %%cluster_ctarank;" : "=r"(crank));
    const int cid = blockIdx.x >> 1;  // cluster id
    const int hd  = cid >> 3;
    const int b0  = (cid & 7) * 8;

    // my two A rows: (gate G, j0) and (gate G, j0+2); j offset by rank*32
    const int j0   = (int)crank * 32 + 4 * wid + q;
    const int rowA = G * 64 + j0;
    const int rowB = rowA + 2;

    // ---- A fragments (weights), bf16x2 hi/lo, register resident ----
    uint32_t ah_hi[4][4], ah_lo[4][4], ax_hi[4], ax_lo[4];
    {
        const float* WhA = W_hh + ((size_t)hd * NGATE + rowA) * HID;
        const float* WhB = W_hh + ((size_t)hd * NGATE + rowB) * HID;
#pragma unroll
        for (int ks = 0; ks < 4; ++ks) {
#pragma unroll
            for (int r = 0; r < 4; ++r) {
                const float* Wr = (r & 1) ? WhB : WhA;
                int kk = 16 * ks + 2 * tg + (r >> 1) * 8;
                __nv_bfloat16 h0, l0, h1, l1;
                split_bf16(Wr[kk],     h0, l0);
                split_bf16(Wr[kk + 1], h1, l1);
                ah_hi[ks][r] = pack_bf16x2(h0, h1);
                ah_lo[ks][r] = pack_bf16x2(l0, l1);
            }
        }
        const float* WiA = W_ih + ((size_t)hd * NGATE + rowA) * NIN;
        const float* WiB = W_ih + ((size_t)hd * NGATE + rowB) * NIN;
#pragma unroll
        for (int r = 0; r < 4; ++r) {
            const float* Wr = (r & 1) ? WiB : WiA;
            int kk = 2 * tg + (r >> 1) * 8;
            __nv_bfloat16 h0, l0, h1, l1;
            split_bf16(Wr[kk],     h0, l0);
            split_bf16(Wr[kk + 1], h1, l1);
            ax_hi[r] = pack_bf16x2(h0, h1);
            ax_lo[r] = pack_bf16x2(l0, l1);
        }
    }
    const float biasA = b_ih[hd * NGATE + rowA] + b_hh[hd * NGATE + rowA];
    const float biasB = b_ih[hd * NGATE + rowB] + b_hh[hd * NGATE + rowB];

    // my output cell after in-warp transpose
    const int jc = (int)crank * 32 + 4 * wid + q + 2 * (G >> 1);
    const int bc = 2 * tg + (G & 1);
    float* gptr = g_hist + ((size_t)(b0 + bc) * NHEAD + hd) * HID + jc;

    // smem: double-buffered full h (both halves), x, mbarrier
    __shared__ __align__(4) __nv_bfloat16 hhi[2][8][72], hlo[2][8][72];
    __shared__ __align__(4) __nv_bfloat16 xhi[2][8][24], xlo[2][8][24];
    __shared__ __align__(8) unsigned long long mbar;

    for (int i = tid; i < 2 * 8 * 72; i += 256) {
        (&hhi[0][0][0])[i] = __float2bfloat16(0.0f);
        (&hlo[0][0][0])[i] = __float2bfloat16(0.0f);
    }
    if (tid == 0) {
        asm volatile("mbarrier.init.shared.b64 [%0], %1;"
                     :: "r"(smem_u32(&mbar)), "r"(512u) : "memory");
    }

    // x loaders: 128 threads cover x[t, b0..b0+7, 0..15]
    float xnext = 0.0f;
    if (tid < 128) {
        int xb = tid >> 4, xf = tid & 15;
        __nv_bfloat16 h0, l0;
        split_bf16(x[((size_t)b0 + xb) * NIN + xf], h0, l0);           // ts = 0
        xhi[0][xb][xf] = h0; xlo[0][xb][xf] = l0;
        xnext = x[(size_t)NBATCH * NIN + (b0 + xb) * NIN + xf];        // ts = 1
    }
    __syncthreads();
    // peer's mbarrier must be initialized before any remote arrive
    asm volatile("barrier.cluster.arrive.aligned;" ::: "memory");
    asm volatile("barrier.cluster.wait.aligned;"   ::: "memory");

    // remote addresses (peer CTA) for my h cell and the peer's mbarrier
    const uint32_t peer = crank ^ 1u;
    const uint32_t l_hi0 = smem_u32(&hhi[0][bc][jc]);
    const uint32_t l_lo0 = smem_u32(&hlo[0][bc][jc]);
    const uint32_t l_mb  = smem_u32(&mbar);
    uint32_t r_hi0, r_lo0, r_mb;
    asm("mapa.shared::cluster.u32 %0, %1, %2;" : "=r"(r_hi0) : "r"(l_hi0), "r"(peer));
    asm("mapa.shared::cluster.u32 %0, %1, %2;" : "=r"(r_lo0) : "r"(l_lo0), "r"(peer));
    asm("mapa.shared::cluster.u32 %0, %1, %2;" : "=r"(r_mb)  : "r"(l_mb),  "r"(peer));
    const uint32_t BUFB = 8 * 72 * 2;          // bytes per h buffer (parity stride)

    float c = 0.0f;
    const unsigned FULL = 0xFFFFFFFFu;

    for (int ts = 0; ts < T_SEQ; ++ts) {
        const int p  = ts & 1;
        const int pn = p ^ 1;

        float d0 = biasA, d1 = biasA, d2 = biasB, d3 = biasB;

        // recurrent: 4 k-steps over hid (B operand = full h, 8 batches)
#pragma unroll
        for (int ks = 0; ks < 4; ++ks) {
            uint32_t bh0 = *reinterpret_cast<const uint32_t*>(&hhi[p][g][16 * ks + 2 * tg]);
            uint32_t bh1 = *reinterpret_cast<const uint32_t*>(&hhi[p][g][16 * ks + 2 * tg + 8]);
            uint32_t bl0 = *reinterpret_cast<const uint32_t*>(&hlo[p][g][16 * ks + 2 * tg]);
            uint32_t bl1 = *reinterpret_cast<const uint32_t*>(&hlo[p][g][16 * ks + 2 * tg + 8]);
            mma16816(d0, d1, d2, d3, ah_hi[ks][0], ah_hi[ks][1], ah_hi[ks][2], ah_hi[ks][3], bh0, bh1);
            mma16816(d0, d1, d2, d3, ah_hi[ks][0], ah_hi[ks][1], ah_hi[ks][2], ah_hi[ks][3], bl0, bl1);
            mma16816(d0, d1, d2, d3, ah_lo[ks][0], ah_lo[ks][1], ah_lo[ks][2], ah_lo[ks][3], bh0, bh1);
        }
        // input: 1 k-step over features
        {
            uint32_t bh0 = *reinterpret_cast<const uint32_t*>(&xhi[p][g][2 * tg]);
            uint32_t bh1 = *reinterpret_cast<const uint32_t*>(&xhi[p][g][2 * tg + 8]);
            uint32_t bl0 = *reinterpret_cast<const uint32_t*>(&xlo[p][g][2 * tg]);
            uint32_t bl1 = *reinterpret_cast<const uint32_t*>(&xlo[p][g][2 * tg + 8]);
            mma16816(d0, d1, d2, d3, ax_hi[0], ax_hi[1], ax_hi[2], ax_hi[3], bh0, bh1);
            mma16816(d0, d1, d2, d3, ax_hi[0], ax_hi[1], ax_hi[2], ax_hi[3], bl0, bl1);
            mma16816(d0, d1, d2, d3, ax_lo[0], ax_lo[1], ax_lo[2], ax_lo[3], bh0, bh1);
        }

        // x double-buffer: publish x(ts+1), fetch x(ts+2)
        if (tid < 128) {
            int xb = tid >> 4, xf = tid & 15;
            __nv_bfloat16 h0, l0;
            split_bf16(xnext, h0, l0);
            xhi[pn][xb][xf] = h0; xlo[pn][xb][xf] = l0;
            int tn = (ts + 2 < T_SEQ) ? ts + 2 : T_SEQ - 1;
            xnext = x[(size_t)tn * NBATCH * NIN + (b0 + xb) * NIN + xf];
        }

        // ---- 4x4 butterfly transpose over gate bits (lane xor 4, xor 8) ----
        {
            float a0 = (G & 1) ? d0 : d1;
            float a1 = (G & 1) ? d2 : d3;
            a0 = __shfl_xor_sync(FULL, a0, 4);
            a1 = __shfl_xor_sync(FULL, a1, 4);
            if (G & 1) { d0 = a0; d2 = a1; } else { d1 = a0; d3 = a1; }
            float e0 = (G & 2) ? d0 : d2;
            float e1 = (G & 2) ? d1 : d3;
            e0 = __shfl_xor_sync(FULL, e0, 8);
            e1 = __shfl_xor_sync(FULL, e1, 8);
            if (G & 2) { d0 = e0; d1 = e1; } else { d2 = e0; d3 = e1; }
        }
        // d0=zi, d1=zf, d2=zg, d3=zo for cell (jc, bc)

        float iv = siga(d0);
        float fv = siga(d1);
        float gv = tanha(d2);
        float ov = siga(d3);
        c = fmaf(fv, c, iv * gv);
        float h = ov * tanha(c);

        __nv_bfloat16 hh, hl;
        split_bf16(h, hh, hl);
        hhi[pn][bc][jc] = hh;                       // local copy
        hlo[pn][bc][jc] = hl;
        {
            // peer copy via DSMEM
            unsigned short uh = *reinterpret_cast<unsigned short*>(&hh);
            unsigned short ul = *reinterpret_cast<unsigned short*>(&hl);
            asm volatile("st.shared::cluster.u16 [%0], %1;"
                         :: "r"(r_hi0 + (uint32_t)pn * BUFB), "h"(uh) : "memory");
            asm volatile("st.shared::cluster.u16 [%0], %1;"
                         :: "r"(r_lo0 + (uint32_t)pn * BUFB), "h"(ul) : "memory");
        }
        gptr[(size_t)ts * (NBATCH * NHEAD * HID)] = h;

        // arrivals: local + remote (release orders the stores above)
        asm volatile("mbarrier.arrive.release.cta.shared::cta.b64 _, [%0];"
                     :: "r"(l_mb) : "memory");
        asm volatile("mbarrier.arrive.release.cluster.shared::cluster.b64 _, [%0];"
                     :: "r"(r_mb) : "memory");

        // wait for this step's 512 arrivals (phase parity = ts&1)
        {
            uint32_t done;
            asm volatile(
                "{\n\t.reg .pred P1;\n\t"
                "mbarrier.try_wait.parity.acquire.cluster.shared::cta.b64 P1, [%1], %2;\n\t"
                "selp.b32 %0, 1, 0, P1;\n\t}"
                : "=r"(done) : "r"(l_mb), "r"((uint32_t)p) : "memory");
            if (!done) {
                asm volatile(
                    "{\n\t.reg .pred P1;\n\t"
                    "WL_%=:\n\t"
                    "mbarrier.try_wait.parity.acquire.cluster.shared::cta.b64 P1, [%0], %1, 0x989680;\n\t"
                    "@P1 bra.uni WD_%=;\n\t"
                    "bra.uni WL_%=;\n\t"
                    "WD_%=:\n\t}"
                    :: "r"(l_mb), "r"((uint32_t)p) : "memory");
            }
        }
    }
}

// ============================================================================
// Epilogue: out[t,b,h] = dot(h, W_lin[h]) + b_lin[h]; lstm_out = sum over heads
// ============================================================================
__global__ __launch_bounds__(256) void lstm_epi_kernel(
    const float* __restrict__ W_lin,
    const float* __restrict__ b_lin,
    float* __restrict__ out,
    float* __restrict__ lstm_out)
{
    const int cell = blockIdx.x * 16 + (threadIdx.x >> 4);
    const int q    = threadIdx.x & 15;

    const float4* hist4 = reinterpret_cast<const float4*>(g_hist) + (size_t)cell * 128;
    float4 v[NHEAD];
#pragma unroll
    for (int h = 0; h < NHEAD; ++h) v[h] = hist4[h * 16 + q];

    float4 s = v[0];
#pragma unroll
    for (int h = 1; h < NHEAD; ++h) { s.x += v[h].x; s.y += v[h].y; s.z += v[h].z; s.w += v[h].w; }
    reinterpret_cast<float4*>(lstm_out)[(size_t)cell * 16 + q] = s;

    const float4* wl4 = reinterpret_cast<const float4*>(W_lin);
    float d[NHEAD];
#pragma unroll
    for (int h = 0; h < NHEAD; ++h) {
        float4 w = wl4[h * 16 + q];
        float acc = v[h].x * w.x;
        acc = fmaf(v[h].y, w.y, acc);
        acc = fmaf(v[h].z, w.z, acc);
        acc = fmaf(v[h].w, w.w, acc);
        d[h] = acc;
    }
#pragma unroll
    for (int off = 8; off > 0; off >>= 1) {
#pragma unroll
        for (int h = 0; h < NHEAD; ++h)
            d[h] += __shfl_xor_sync(0xFFFFFFFFu, d[h], off);
    }
    if (q == 0) {
#pragma unroll
        for (int h = 0; h < NHEAD; ++h)
            out[(size_t)cell * NHEAD + h] = d[h] + b_lin[h];
    }
}

extern "C" void kernel_launch(void* const* d_in, const int* in_sizes, int n_in,
                              void* d_out, int out_size) {
    const float* x     = (const float*)d_in[0];
    const float* W_ih  = (const float*)d_in[1];
    const float* W_hh  = (const float*)d_in[2];
    const float* b_ih  = (const float*)d_in[3];
    const float* b_hh  = (const float*)d_in[4];
    const float* W_lin = (const float*)d_in[5];
    const float* b_lin = (const float*)d_in[6];

    float* out      = (float*)d_out;                         // (T,B,H)
    float* lstm_out = out + (size_t)T_SEQ * NBATCH * NHEAD;  // (T,B,HID)

    lstm_rec_mma<<<2 * NHEAD * (NBATCH / 8), 256>>>(x, W_ih, W_hh, b_ih, b_hh);
    lstm_epi_kernel<<<(T_SEQ * NBATCH) / 16, 256>>>(W_lin, b_lin, out, lstm_out);
}

// round 10
// speedup vs baseline: 1.7187x; 1.7187x over previous
#include <cuda_runtime.h>
#include <cuda_bf16.h>
#include <cstdint>

#define T_SEQ 2048
#define NBATCH 64
#define NIN 16
#define NHEAD 8
#define HID 64
#define NGATE 256

// h history scratch (device global; no runtime allocation)
__device__ float g_hist[(size_t)T_SEQ * NBATCH * NHEAD * HID];   // 256 MB

// ---- helpers ----
__device__ __forceinline__ uint32_t pack_bf16x2(__nv_bfloat16 a, __nv_bfloat16 b) {
    __nv_bfloat162 v; v.x = a; v.y = b;
    return *reinterpret_cast<uint32_t*>(&v);
}
__device__ __forceinline__ void split_bf16(float f, __nv_bfloat16& hi, __nv_bfloat16& lo) {
    hi = __float2bfloat16_rn(f);
    lo = __float2bfloat16_rn(f - __bfloat162float(hi));
}
__device__ __forceinline__ void mma16816(float& d0, float& d1, float& d2, float& d3,
                                         uint32_t a0, uint32_t a1, uint32_t a2, uint32_t a3,
                                         uint32_t b0, uint32_t b1) {
    asm volatile(
        "mma.sync.aligned.m16n8k16.row.col.f32.bf16.bf16.f32 "
        "{%0,%1,%2,%3},{%4,%5,%6,%7},{%8,%9},{%0,%1,%2,%3};"
        : "+f"(d0), "+f"(d1), "+f"(d2), "+f"(d3)
        : "r"(a0), "r"(a1), "r"(a2), "r"(a3), "r"(b0), "r"(b1));
}
__device__ __forceinline__ float tanha(float x) {
    float y; asm("tanh.approx.f32 %0, %1;" : "=f"(y) : "f"(x)); return y;
}
__device__ __forceinline__ float siga(float z) {          // 1 MUFU sigmoid
    return fmaf(0.5f, tanha(0.5f * z), 0.5f);
}

// ============================================================================
// Recurrent kernel, bf16 m16n8k16, gate-permuted tiles + register transpose.
// Grid: 64 CTAs = head(8) x batch-group(8). Block: 512 (16 warps).
// Warp w's m16 tile rows = permuted gate rows: tile row r -> global row
// (r&3)*64 + (4w + (r>>2)), so the warp owns ALL FOUR gates of cells
// j in [4w, 4w+4) x 8 batches. 15 HMMA/step (3-term bf16 split, fp32 acc)
// spread across THREE independent accumulator sets (p,q,r) so the RAW chain
// depth is 5 instead of 15; z = p+q+r. Then a 4-shuffle butterfly transpose
// gives each lane (zi,zf,zg,zo) of one cell -> in-warp activation, ONE
// barrier per step.
// ============================================================================
__global__ __launch_bounds__(512, 1) void lstm_rec_mma(
    const float* __restrict__ x,     // (T,B,16)
    const float* __restrict__ W_ih,  // (8,256,16)
    const float* __restrict__ W_hh,  // (8,256,64)
    const float* __restrict__ b_ih,  // (8,256)
    const float* __restrict__ b_hh)  // (8,256)
{
    const int tid  = threadIdx.x;
    const int wid  = tid >> 5;
    const int lane = tid & 31;
    const int g    = lane >> 2;       // fragment group id
    const int tg   = lane & 3;
    const int G    = g & 3;           // gate of this lane's A rows
    const int q    = g >> 2;          // j-slot base (0 or 1)
    const int hd   = blockIdx.x >> 3;
    const int b0   = (blockIdx.x & 7) * 8;

    // my two A rows: (gate G, j0) and (gate G, j0+2)
    const int j0 = 4 * wid + q;
    const int rowA = G * 64 + j0;          // local gate row, tile rows g / g+8
    const int rowB = rowA + 2;

    // ---- A fragments (weights), bf16x2 hi/lo, register resident ----
    uint32_t ah_hi[4][4], ah_lo[4][4], ax_hi[4], ax_lo[4];
    {
        const float* WhA = W_hh + ((size_t)hd * NGATE + rowA) * HID;
        const float* WhB = W_hh + ((size_t)hd * NGATE + rowB) * HID;
#pragma unroll
        for (int ks = 0; ks < 4; ++ks) {
#pragma unroll
            for (int r = 0; r < 4; ++r) {
                const float* Wr = (r & 1) ? WhB : WhA;
                int kk = 16 * ks + 2 * tg + (r >> 1) * 8;
                __nv_bfloat16 h0, l0, h1, l1;
                split_bf16(Wr[kk],     h0, l0);
                split_bf16(Wr[kk + 1], h1, l1);
                ah_hi[ks][r] = pack_bf16x2(h0, h1);
                ah_lo[ks][r] = pack_bf16x2(l0, l1);
            }
        }
        const float* WiA = W_ih + ((size_t)hd * NGATE + rowA) * NIN;
        const float* WiB = W_ih + ((size_t)hd * NGATE + rowB) * NIN;
#pragma unroll
        for (int r = 0; r < 4; ++r) {
            const float* Wr = (r & 1) ? WiB : WiA;
            int kk = 2 * tg + (r >> 1) * 8;
            __nv_bfloat16 h0, l0, h1, l1;
            split_bf16(Wr[kk],     h0, l0);
            split_bf16(Wr[kk + 1], h1, l1);
            ax_hi[r] = pack_bf16x2(h0, h1);
            ax_lo[r] = pack_bf16x2(l0, l1);
        }
    }
    // accumulator bias seeds (row bias, same for both batch cols)
    const float biasA = b_ih[hd * NGATE + rowA] + b_hh[hd * NGATE + rowA];
    const float biasB = b_ih[hd * NGATE + rowB] + b_hh[hd * NGATE + rowB];

    // my output cell after transpose
    const int jc = 4 * wid + q + 2 * (G >> 1);
    const int bc = 2 * tg + (G & 1);
    float* gptr = g_hist + ((size_t)(b0 + bc) * NHEAD + hd) * HID + jc;

    // smem: double-buffered h (hi/lo bf16) and x
    __shared__ __align__(4) __nv_bfloat16 hhi[2][8][72], hlo[2][8][72];
    __shared__ __align__(4) __nv_bfloat16 xhi[2][8][24], xlo[2][8][24];

    for (int i = tid; i < 2 * 8 * 72; i += 512) {
        (&hhi[0][0][0])[i] = __float2bfloat16(0.0f);
        (&hlo[0][0][0])[i] = __float2bfloat16(0.0f);
    }

    // x loaders: 128 threads cover x[t, b0..b0+7, 0..15]
    float xnext = 0.0f;
    if (tid < 128) {
        int xb = tid >> 4, xf = tid & 15;
        __nv_bfloat16 h0, l0;
        split_bf16(x[((size_t)b0 + xb) * NIN + xf], h0, l0);           // ts = 0
        xhi[0][xb][xf] = h0; xlo[0][xb][xf] = l0;
        xnext = x[(size_t)NBATCH * NIN + (b0 + xb) * NIN + xf];        // ts = 1
    }

    float c = 0.0f;
    const unsigned FULL = 0xFFFFFFFFu;

    for (int ts = 0; ts < T_SEQ; ++ts) {
        const int p = ts & 1;
        __syncthreads();                 // h(ts-1) in buf p, x(ts) in buf p visible

        // three independent accumulator sets -> RAW chain depth 5, not 15
        float p0 = biasA, p1 = biasA, p2 = biasB, p3 = biasB;
        float q0 = 0.0f,  q1 = 0.0f,  q2 = 0.0f,  q3 = 0.0f;
        float r0 = 0.0f,  r1 = 0.0f,  r2 = 0.0f,  r3 = 0.0f;

        // recurrent: 4 k-steps over hid
#pragma unroll
        for (int ks = 0; ks < 4; ++ks) {
            uint32_t bh0 = *reinterpret_cast<const uint32_t*>(&hhi[p][g][16 * ks + 2 * tg]);
            uint32_t bh1 = *reinterpret_cast<const uint32_t*>(&hhi[p][g][16 * ks + 2 * tg + 8]);
            uint32_t bl0 = *reinterpret_cast<const uint32_t*>(&hlo[p][g][16 * ks + 2 * tg]);
            uint32_t bl1 = *reinterpret_cast<const uint32_t*>(&hlo[p][g][16 * ks + 2 * tg + 8]);
            mma16816(p0, p1, p2, p3, ah_hi[ks][0], ah_hi[ks][1], ah_hi[ks][2], ah_hi[ks][3], bh0, bh1);
            mma16816(q0, q1, q2, q3, ah_hi[ks][0], ah_hi[ks][1], ah_hi[ks][2], ah_hi[ks][3], bl0, bl1);
            mma16816(r0, r1, r2, r3, ah_lo[ks][0], ah_lo[ks][1], ah_lo[ks][2], ah_lo[ks][3], bh0, bh1);
        }
        // input: 1 k-step over features (one MMA per accumulator set)
        {
            uint32_t bh0 = *reinterpret_cast<const uint32_t*>(&xhi[p][g][2 * tg]);
            uint32_t bh1 = *reinterpret_cast<const uint32_t*>(&xhi[p][g][2 * tg + 8]);
            uint32_t bl0 = *reinterpret_cast<const uint32_t*>(&xlo[p][g][2 * tg]);
            uint32_t bl1 = *reinterpret_cast<const uint32_t*>(&xlo[p][g][2 * tg + 8]);
            mma16816(p0, p1, p2, p3, ax_hi[0], ax_hi[1], ax_hi[2], ax_hi[3], bh0, bh1);
            mma16816(q0, q1, q2, q3, ax_hi[0], ax_hi[1], ax_hi[2], ax_hi[3], bl0, bl1);
            mma16816(r0, r1, r2, r3, ax_lo[0], ax_lo[1], ax_lo[2], ax_lo[3], bh0, bh1);
        }

        // x double-buffer: publish x(ts+1), fetch x(ts+2) (off critical path)
        if (tid < 128) {
            int xb = tid >> 4, xf = tid & 15;
            __nv_bfloat16 h0, l0;
            split_bf16(xnext, h0, l0);
            xhi[p ^ 1][xb][xf] = h0; xlo[p ^ 1][xb][xf] = l0;
            int tn = (ts + 2 < T_SEQ) ? ts + 2 : T_SEQ - 1;
            xnext = x[(size_t)tn * NBATCH * NIN + (b0 + xb) * NIN + xf];
        }

        // combine accumulator sets
        float d0 = p0 + (q0 + r0);
        float d1 = p1 + (q1 + r1);
        float d2 = p2 + (q2 + r2);
        float d3 = p3 + (q3 + r3);

        // ---- 4x4 butterfly transpose over gate bits (lane xor 4, xor 8) ----
        {
            float a0 = (G & 1) ? d0 : d1;
            float a1 = (G & 1) ? d2 : d3;
            a0 = __shfl_xor_sync(FULL, a0, 4);
            a1 = __shfl_xor_sync(FULL, a1, 4);
            if (G & 1) { d0 = a0; d2 = a1; } else { d1 = a0; d3 = a1; }
            float e0 = (G & 2) ? d0 : d2;
            float e1 = (G & 2) ? d1 : d3;
            e0 = __shfl_xor_sync(FULL, e0, 8);
            e1 = __shfl_xor_sync(FULL, e1, 8);
            if (G & 2) { d0 = e0; d1 = e1; } else { d2 = e0; d3 = e1; }
        }
        // now d0=zi, d1=zf, d2=zg, d3=zo for cell (jc, bc)

        float iv = siga(d0);
        float fv = siga(d1);
        float gv = tanha(d2);
        float ov = siga(d3);
        c = fmaf(fv, c, iv * gv);
        float h = ov * tanha(c);

        __nv_bfloat16 hh, hl;
        split_bf16(h, hh, hl);
        hhi[p ^ 1][bc][jc] = hh;
        hlo[p ^ 1][bc][jc] = hl;
        gptr[(size_t)ts * (NBATCH * NHEAD * HID)] = h;
        // loop-top barrier publishes buf p^1 for step ts+1
    }
}

// ============================================================================
// Epilogue: out[t,b,h] = dot(h, W_lin[h]) + b_lin[h]; lstm_out = sum over heads
// ============================================================================
__global__ __launch_bounds__(256) void lstm_epi_kernel(
    const float* __restrict__ W_lin,
    const float* __restrict__ b_lin,
    float* __restrict__ out,
    float* __restrict__ lstm_out)
{
    const int cell = blockIdx.x * 16 + (threadIdx.x >> 4);
    const int q    = threadIdx.x & 15;

    const float4* hist4 = reinterpret_cast<const float4*>(g_hist) + (size_t)cell * 128;
    float4 v[NHEAD];
#pragma unroll
    for (int h = 0; h < NHEAD; ++h) v[h] = hist4[h * 16 + q];

    float4 s = v[0];
#pragma unroll
    for (int h = 1; h < NHEAD; ++h) { s.x += v[h].x; s.y += v[h].y; s.z += v[h].z; s.w += v[h].w; }
    reinterpret_cast<float4*>(lstm_out)[(size_t)cell * 16 + q] = s;

    const float4* wl4 = reinterpret_cast<const float4*>(W_lin);
    float d[NHEAD];
#pragma unroll
    for (int h = 0; h < NHEAD; ++h) {
        float4 w = wl4[h * 16 + q];
        float acc = v[h].x * w.x;
        acc = fmaf(v[h].y, w.y, acc);
        acc = fmaf(v[h].z, w.z, acc);
        acc = fmaf(v[h].w, w.w, acc);
        d[h] = acc;
    }
#pragma unroll
    for (int off = 8; off > 0; off >>= 1) {
#pragma unroll
        for (int h = 0; h < NHEAD; ++h)
            d[h] += __shfl_xor_sync(0xFFFFFFFFu, d[h], off);
    }
    if (q == 0) {
#pragma unroll
        for (int h = 0; h < NHEAD; ++h)
            out[(size_t)cell * NHEAD + h] = d[h] + b_lin[h];
    }
}

extern "C" void kernel_launch(void* const* d_in, const int* in_sizes, int n_in,
                              void* d_out, int out_size) {
    const float* x     = (const float*)d_in[0];
    const float* W_ih  = (const float*)d_in[1];
    const float* W_hh  = (const float*)d_in[2];
    const float* b_ih  = (const float*)d_in[3];
    const float* b_hh  = (const float*)d_in[4];
    const float* W_lin = (const float*)d_in[5];
    const float* b_lin = (const float*)d_in[6];

    float* out      = (float*)d_out;                         // (T,B,H)
    float* lstm_out = out + (size_t)T_SEQ * NBATCH * NHEAD;  // (T,B,HID)

    lstm_rec_mma<<<NHEAD * (NBATCH / 8), 512>>>(x, W_ih, W_hh, b_ih, b_hh);
    lstm_epi_kernel<<<(T_SEQ * NBATCH) / 16, 256>>>(W_lin, b_lin, out, lstm_out);
}

// round 12
// speedup vs baseline: 2.0478x; 1.1915x over previous
#include <cuda_runtime.h>
#include <cuda_fp16.h>
#include <cstdint>

#define T_SEQ 2048
#define NBATCH 64
#define NIN 16
#define NHEAD 8
#define HID 64
#define NGATE 256

// h history scratch (device global; no runtime allocation)
__device__ float g_hist[(size_t)T_SEQ * NBATCH * NHEAD * HID];   // 256 MB

// ---- helpers ----
__device__ __forceinline__ uint32_t pack_h2(__half a, __half b) {
    __half2 v; v.x = a; v.y = b;
    return *reinterpret_cast<uint32_t*>(&v);
}
__device__ __forceinline__ void split_f16(float f, __half& hi, __half& lo) {
    hi = __float2half_rn(f);
    lo = __float2half_rn(f - __half2float(hi));
}
__device__ __forceinline__ void mma16816(float& d0, float& d1, float& d2, float& d3,
                                         uint32_t a0, uint32_t a1, uint32_t a2, uint32_t a3,
                                         uint32_t b0, uint32_t b1) {
    asm volatile(
        "mma.sync.aligned.m16n8k16.row.col.f32.f16.f16.f32 "
        "{%0,%1,%2,%3},{%4,%5,%6,%7},{%8,%9},{%0,%1,%2,%3};"
        : "+f"(d0), "+f"(d1), "+f"(d2), "+f"(d3)
        : "r"(a0), "r"(a1), "r"(a2), "r"(a3), "r"(b0), "r"(b1));
}
__device__ __forceinline__ float tanha(float x) {
    float y; asm("tanh.approx.f32 %0, %1;" : "=f"(y) : "f"(x)); return y;
}
__device__ __forceinline__ float siga(float z) {          // 1 MUFU sigmoid
    return fmaf(0.5f, tanha(0.5f * z), 0.5f);
}

// ============================================================================
// Recurrent kernel, fp16 m16n8k16, gate-permuted tiles + register transpose.
// Grid: 64 CTAs = head(8) x batch-group(8). Block: 512 (16 warps).
// Warp w's m16 tile rows = permuted gate rows: tile row r -> global row
// (r&3)*64 + (4w + (r>>2)), so the warp owns ALL FOUR gates of cells
// j in [4w, 4w+4) x 8 batches. 2-term fp16 split: W single fp16 (static
// rounding ~2^-11), B (h/x) split hi+lo -> W*Bhi + W*Blo, fp32 accumulate:
// 10 HMMA/warp/step. After the MMAs a 4-shuffle butterfly transpose gives
// each lane (zi,zf,zg,zo) of one cell -> in-warp activation, ONE barrier/step.
// ============================================================================
__global__ __launch_bounds__(512, 1) void lstm_rec_mma(
    const float* __restrict__ x,     // (T,B,16)
    const float* __restrict__ W_ih,  // (8,256,16)
    const float* __restrict__ W_hh,  // (8,256,64)
    const float* __restrict__ b_ih,  // (8,256)
    const float* __restrict__ b_hh)  // (8,256)
{
    const int tid  = threadIdx.x;
    const int wid  = tid >> 5;
    const int lane = tid & 31;
    const int g    = lane >> 2;       // fragment group id
    const int tg   = lane & 3;
    const int G    = g & 3;           // gate of this lane's A rows
    const int q    = g >> 2;          // j-slot base (0 or 1)
    const int hd   = blockIdx.x >> 3;
    const int b0   = (blockIdx.x & 7) * 8;

    // my two A rows: (gate G, j0) and (gate G, j0+2)
    const int j0 = 4 * wid + q;
    const int rowA = G * 64 + j0;          // local gate row, tile rows g / g+8
    const int rowB = rowA + 2;

    // ---- A fragments (weights), single fp16x2, register resident ----
    uint32_t ah[4][4], ax[4];
    {
        const float* WhA = W_hh + ((size_t)hd * NGATE + rowA) * HID;
        const float* WhB = W_hh + ((size_t)hd * NGATE + rowB) * HID;
#pragma unroll
        for (int ks = 0; ks < 4; ++ks) {
#pragma unroll
            for (int r = 0; r < 4; ++r) {
                const float* Wr = (r & 1) ? WhB : WhA;
                int kk = 16 * ks + 2 * tg + (r >> 1) * 8;
                ah[ks][r] = pack_h2(__float2half_rn(Wr[kk]), __float2half_rn(Wr[kk + 1]));
            }
        }
        const float* WiA = W_ih + ((size_t)hd * NGATE + rowA) * NIN;
        const float* WiB = W_ih + ((size_t)hd * NGATE + rowB) * NIN;
#pragma unroll
        for (int r = 0; r < 4; ++r) {
            const float* Wr = (r & 1) ? WiB : WiA;
            int kk = 2 * tg + (r >> 1) * 8;
            ax[r] = pack_h2(__float2half_rn(Wr[kk]), __float2half_rn(Wr[kk + 1]));
        }
    }
    // accumulator bias seeds (row bias, same for both batch cols)
    const float biasA = b_ih[hd * NGATE + rowA] + b_hh[hd * NGATE + rowA];
    const float biasB = b_ih[hd * NGATE + rowB] + b_hh[hd * NGATE + rowB];

    // my output cell after transpose
    const int jc = 4 * wid + q + 2 * (G >> 1);
    const int bc = 2 * tg + (G & 1);
    float* gptr = g_hist + ((size_t)(b0 + bc) * NHEAD + hd) * HID + jc;

    // smem: double-buffered h (hi/lo fp16) and x
    __shared__ __align__(4) __half hhi[2][8][72], hlo[2][8][72];
    __shared__ __align__(4) __half xhi[2][8][24], xlo[2][8][24];

    for (int i = tid; i < 2 * 8 * 72; i += 512) {
        (&hhi[0][0][0])[i] = __float2half(0.0f);
        (&hlo[0][0][0])[i] = __float2half(0.0f);
    }

    // x loaders: 128 threads cover x[t, b0..b0+7, 0..15]
    float xnext = 0.0f;
    if (tid < 128) {
        int xb = tid >> 4, xf = tid & 15;
        __half h0, l0;
        split_f16(x[((size_t)b0 + xb) * NIN + xf], h0, l0);            // ts = 0
        xhi[0][xb][xf] = h0; xlo[0][xb][xf] = l0;
        xnext = x[(size_t)NBATCH * NIN + (b0 + xb) * NIN + xf];        // ts = 1
    }

    float c = 0.0f;
    const unsigned FULL = 0xFFFFFFFFu;

    for (int ts = 0; ts < T_SEQ; ++ts) {
        const int p = ts & 1;
        __syncthreads();                 // h(ts-1) in buf p, x(ts) in buf p visible

        float d0 = biasA, d1 = biasA, d2 = biasB, d3 = biasB;

        // recurrent: 4 k-steps over hid, 2 MMAs each (W*Bhi + W*Blo)
#pragma unroll
        for (int ks = 0; ks < 4; ++ks) {
            uint32_t bh0 = *reinterpret_cast<const uint32_t*>(&hhi[p][g][16 * ks + 2 * tg]);
            uint32_t bh1 = *reinterpret_cast<const uint32_t*>(&hhi[p][g][16 * ks + 2 * tg + 8]);
            uint32_t bl0 = *reinterpret_cast<const uint32_t*>(&hlo[p][g][16 * ks + 2 * tg]);
            uint32_t bl1 = *reinterpret_cast<const uint32_t*>(&hlo[p][g][16 * ks + 2 * tg + 8]);
            mma16816(d0, d1, d2, d3, ah[ks][0], ah[ks][1], ah[ks][2], ah[ks][3], bh0, bh1);
            mma16816(d0, d1, d2, d3, ah[ks][0], ah[ks][1], ah[ks][2], ah[ks][3], bl0, bl1);
        }
        // input: 1 k-step over features, 2 MMAs
        {
            uint32_t bh0 = *reinterpret_cast<const uint32_t*>(&xhi[p][g][2 * tg]);
            uint32_t bh1 = *reinterpret_cast<const uint32_t*>(&xhi[p][g][2 * tg + 8]);
            uint32_t bl0 = *reinterpret_cast<const uint32_t*>(&xlo[p][g][2 * tg]);
            uint32_t bl1 = *reinterpret_cast<const uint32_t*>(&xlo[p][g][2 * tg + 8]);
            mma16816(d0, d1, d2, d3, ax[0], ax[1], ax[2], ax[3], bh0, bh1);
            mma16816(d0, d1, d2, d3, ax[0], ax[1], ax[2], ax[3], bl0, bl1);
        }

        // x double-buffer: publish x(ts+1), fetch x(ts+2) (off critical path)
        if (tid < 128) {
            int xb = tid >> 4, xf = tid & 15;
            __half h0, l0;
            split_f16(xnext, h0, l0);
            xhi[p ^ 1][xb][xf] = h0; xlo[p ^ 1][xb][xf] = l0;
            int tn = (ts + 2 < T_SEQ) ? ts + 2 : T_SEQ - 1;
            xnext = x[(size_t)tn * NBATCH * NIN + (b0 + xb) * NIN + xf];
        }

        // ---- 4x4 butterfly transpose over gate bits (lane xor 4, xor 8) ----
        {
            float a0 = (G & 1) ? d0 : d1;
            float a1 = (G & 1) ? d2 : d3;
            a0 = __shfl_xor_sync(FULL, a0, 4);
            a1 = __shfl_xor_sync(FULL, a1, 4);
            if (G & 1) { d0 = a0; d2 = a1; } else { d1 = a0; d3 = a1; }
            float e0 = (G & 2) ? d0 : d2;
            float e1 = (G & 2) ? d1 : d3;
            e0 = __shfl_xor_sync(FULL, e0, 8);
            e1 = __shfl_xor_sync(FULL, e1, 8);
            if (G & 2) { d0 = e0; d1 = e1; } else { d2 = e0; d3 = e1; }
        }
        // now d0=zi, d1=zf, d2=zg, d3=zo for cell (jc, bc)

        float iv = siga(d0);
        float fv = siga(d1);
        float gv = tanha(d2);
        float ov = siga(d3);
        c = fmaf(fv, c, iv * gv);
        float h = ov * tanha(c);

        __half hh, hl;
        split_f16(h, hh, hl);
        hhi[p ^ 1][bc][jc] = hh;
        hlo[p ^ 1][bc][jc] = hl;
        gptr[(size_t)ts * (NBATCH * NHEAD * HID)] = h;
        // loop-top barrier publishes buf p^1 for step ts+1
    }
}

// ============================================================================
// Epilogue: out[t,b,h] = dot(h, W_lin[h]) + b_lin[h]; lstm_out = sum over heads
// ============================================================================
__global__ __launch_bounds__(256) void lstm_epi_kernel(
    const float* __restrict__ W_lin,
    const float* __restrict__ b_lin,
    float* __restrict__ out,
    float* __restrict__ lstm_out)
{
    const int cell = blockIdx.x * 16 + (threadIdx.x >> 4);
    const int q    = threadIdx.x & 15;

    const float4* hist4 = reinterpret_cast<const float4*>(g_hist) + (size_t)cell * 128;
    float4 v[NHEAD];
#pragma unroll
    for (int h = 0; h < NHEAD; ++h) v[h] = hist4[h * 16 + q];

    float4 s = v[0];
#pragma unroll
    for (int h = 1; h < NHEAD; ++h) { s.x += v[h].x; s.y += v[h].y; s.z += v[h].z; s.w += v[h].w; }
    reinterpret_cast<float4*>(lstm_out)[(size_t)cell * 16 + q] = s;

    const float4* wl4 = reinterpret_cast<const float4*>(W_lin);
    float d[NHEAD];
#pragma unroll
    for (int h = 0; h < NHEAD; ++h) {
        float4 w = wl4[h * 16 + q];
        float acc = v[h].x * w.x;
        acc = fmaf(v[h].y, w.y, acc);
        acc = fmaf(v[h].z, w.z, acc);
        acc = fmaf(v[h].w, w.w, acc);
        d[h] = acc;
    }
#pragma unroll
    for (int off = 8; off > 0; off >>= 1) {
#pragma unroll
        for (int h = 0; h < NHEAD; ++h)
            d[h] += __shfl_xor_sync(0xFFFFFFFFu, d[h], off);
    }
    if (q == 0) {
#pragma unroll
        for (int h = 0; h < NHEAD; ++h)
            out[(size_t)cell * NHEAD + h] = d[h] + b_lin[h];
    }
}

extern "C" void kernel_launch(void* const* d_in, const int* in_sizes, int n_in,
                              void* d_out, int out_size) {
    const float* x     = (const float*)d_in[0];
    const float* W_ih  = (const float*)d_in[1];
    const float* W_hh  = (const float*)d_in[2];
    const float* b_ih  = (const float*)d_in[3];
    const float* b_hh  = (const float*)d_in[4];
    const float* W_lin = (const float*)d_in[5];
    const float* b_lin = (const float*)d_in[6];

    float* out      = (float*)d_out;                         // (T,B,H)
    float* lstm_out = out + (size_t)T_SEQ * NBATCH * NHEAD;  // (T,B,HID)

    lstm_rec_mma<<<NHEAD * (NBATCH / 8), 512>>>(x, W_ih, W_hh, b_ih, b_hh);
    lstm_epi_kernel<<<(T_SEQ * NBATCH) / 16, 256>>>(W_lin, b_lin, out, lstm_out);
}

// round 13
// speedup vs baseline: 2.1354x; 1.0427x over previous
#include <cuda_runtime.h>
#include <cuda_fp16.h>
#include <cstdint>

#define T_SEQ 2048
#define NBATCH 64
#define NIN 16
#define NHEAD 8
#define HID 64
#define NGATE 256

// h history scratch (device global; no runtime allocation)
__device__ float g_hist[(size_t)T_SEQ * NBATCH * NHEAD * HID];   // 256 MB

// ---- helpers ----
__device__ __forceinline__ uint32_t pack_h2(__half a, __half b) {
    __half2 v; v.x = a; v.y = b;
    return *reinterpret_cast<uint32_t*>(&v);
}
__device__ __forceinline__ void split_f16(float f, __half& hi, __half& lo) {
    hi = __float2half_rn(f);
    lo = __float2half_rn(f - __half2float(hi));
}
__device__ __forceinline__ void mma16816(float& d0, float& d1, float& d2, float& d3,
                                         uint32_t a0, uint32_t a1, uint32_t a2, uint32_t a3,
                                         uint32_t b0, uint32_t b1) {
    asm volatile(
        "mma.sync.aligned.m16n8k16.row.col.f32.f16.f16.f32 "
        "{%0,%1,%2,%3},{%4,%5,%6,%7},{%8,%9},{%0,%1,%2,%3};"
        : "+f"(d0), "+f"(d1), "+f"(d2), "+f"(d3)
        : "r"(a0), "r"(a1), "r"(a2), "r"(a3), "r"(b0), "r"(b1));
}
__device__ __forceinline__ float tanha(float x) {
    float y; asm("tanh.approx.f32 %0, %1;" : "=f"(y) : "f"(x)); return y;
}
__device__ __forceinline__ float siga(float z) {          // 1 MUFU sigmoid
    return fmaf(0.5f, tanha(0.5f * z), 0.5f);
}

// ============================================================================
// Recurrent kernel, fp16 m16n8k16, gate-permuted tiles + register transpose.
// Grid: 64 CTAs = head(8) x batch-group(8). Block: 512 (16 warps).
// Warp w's m16 tile rows = permuted gate rows: tile row r -> global row
// (r&3)*64 + (4w + (r>>2)), so the warp owns ALL FOUR gates of cells
// j in [4w, 4w+4) x 8 batches.
// Precision scheme: W fp16-rounded (systematic ~2^-11 -> measured 1.6e-4),
// h stored single fp16 (quasi-random per-step ~2^-11, cancels), x split
// hi+lo 2-term. 4 h-MMAs + 2 x-MMAs = 6 HMMA/warp/step, fp32 accumulate.
// After the MMAs a 4-shuffle butterfly transpose gives each lane
// (zi,zf,zg,zo) of one cell -> in-warp activation, ONE barrier per step.
// ============================================================================
__global__ __launch_bounds__(512, 1) void lstm_rec_mma(
    const float* __restrict__ x,     // (T,B,16)
    const float* __restrict__ W_ih,  // (8,256,16)
    const float* __restrict__ W_hh,  // (8,256,64)
    const float* __restrict__ b_ih,  // (8,256)
    const float* __restrict__ b_hh)  // (8,256)
{
    const int tid  = threadIdx.x;
    const int wid  = tid >> 5;
    const int lane = tid & 31;
    const int g    = lane >> 2;       // fragment group id
    const int tg   = lane & 3;
    const int G    = g & 3;           // gate of this lane's A rows
    const int q    = g >> 2;          // j-slot base (0 or 1)
    const int hd   = blockIdx.x >> 3;
    const int b0   = (blockIdx.x & 7) * 8;

    // my two A rows: (gate G, j0) and (gate G, j0+2)
    const int j0 = 4 * wid + q;
    const int rowA = G * 64 + j0;          // local gate row, tile rows g / g+8
    const int rowB = rowA + 2;

    // ---- A fragments (weights), single fp16x2, register resident ----
    uint32_t ah[4][4], ax[4];
    {
        const float* WhA = W_hh + ((size_t)hd * NGATE + rowA) * HID;
        const float* WhB = W_hh + ((size_t)hd * NGATE + rowB) * HID;
#pragma unroll
        for (int ks = 0; ks < 4; ++ks) {
#pragma unroll
            for (int r = 0; r < 4; ++r) {
                const float* Wr = (r & 1) ? WhB : WhA;
                int kk = 16 * ks + 2 * tg + (r >> 1) * 8;
                ah[ks][r] = pack_h2(__float2half_rn(Wr[kk]), __float2half_rn(Wr[kk + 1]));
            }
        }
        const float* WiA = W_ih + ((size_t)hd * NGATE + rowA) * NIN;
        const float* WiB = W_ih + ((size_t)hd * NGATE + rowB) * NIN;
#pragma unroll
        for (int r = 0; r < 4; ++r) {
            const float* Wr = (r & 1) ? WiB : WiA;
            int kk = 2 * tg + (r >> 1) * 8;
            ax[r] = pack_h2(__float2half_rn(Wr[kk]), __float2half_rn(Wr[kk + 1]));
        }
    }
    // accumulator bias seeds (row bias, same for both batch cols)
    const float biasA = b_ih[hd * NGATE + rowA] + b_hh[hd * NGATE + rowA];
    const float biasB = b_ih[hd * NGATE + rowB] + b_hh[hd * NGATE + rowB];

    // my output cell after transpose
    const int jc = 4 * wid + q + 2 * (G >> 1);
    const int bc = 2 * tg + (G & 1);
    float* gptr = g_hist + ((size_t)(b0 + bc) * NHEAD + hd) * HID + jc;

    // smem: double-buffered h (single fp16) and x (hi/lo fp16)
    __shared__ __align__(4) __half hsm[2][8][72];
    __shared__ __align__(4) __half xhi[2][8][24], xlo[2][8][24];

    for (int i = tid; i < 2 * 8 * 72; i += 512)
        (&hsm[0][0][0])[i] = __float2half(0.0f);

    // x loaders: 128 threads cover x[t, b0..b0+7, 0..15]
    float xnext = 0.0f;
    if (tid < 128) {
        int xb = tid >> 4, xf = tid & 15;
        __half h0, l0;
        split_f16(x[((size_t)b0 + xb) * NIN + xf], h0, l0);            // ts = 0
        xhi[0][xb][xf] = h0; xlo[0][xb][xf] = l0;
        xnext = x[(size_t)NBATCH * NIN + (b0 + xb) * NIN + xf];        // ts = 1
    }

    float c = 0.0f;
    const unsigned FULL = 0xFFFFFFFFu;

    for (int ts = 0; ts < T_SEQ; ++ts) {
        const int p = ts & 1;
        __syncthreads();                 // h(ts-1) in buf p, x(ts) in buf p visible

        float d0 = biasA, d1 = biasA, d2 = biasB, d3 = biasB;

        // recurrent: 4 k-steps over hid, 1 MMA each (W * h16)
#pragma unroll
        for (int ks = 0; ks < 4; ++ks) {
            uint32_t bh0 = *reinterpret_cast<const uint32_t*>(&hsm[p][g][16 * ks + 2 * tg]);
            uint32_t bh1 = *reinterpret_cast<const uint32_t*>(&hsm[p][g][16 * ks + 2 * tg + 8]);
            mma16816(d0, d1, d2, d3, ah[ks][0], ah[ks][1], ah[ks][2], ah[ks][3], bh0, bh1);
        }
        // input: 1 k-step over features, 2 MMAs (W*xhi + W*xlo)
        {
            uint32_t bh0 = *reinterpret_cast<const uint32_t*>(&xhi[p][g][2 * tg]);
            uint32_t bh1 = *reinterpret_cast<const uint32_t*>(&xhi[p][g][2 * tg + 8]);
            uint32_t bl0 = *reinterpret_cast<const uint32_t*>(&xlo[p][g][2 * tg]);
            uint32_t bl1 = *reinterpret_cast<const uint32_t*>(&xlo[p][g][2 * tg + 8]);
            mma16816(d0, d1, d2, d3, ax[0], ax[1], ax[2], ax[3], bh0, bh1);
            mma16816(d0, d1, d2, d3, ax[0], ax[1], ax[2], ax[3], bl0, bl1);
        }

        // x double-buffer: publish x(ts+1), fetch x(ts+2) (off critical path)
        if (tid < 128) {
            int xb = tid >> 4, xf = tid & 15;
            __half h0, l0;
            split_f16(xnext, h0, l0);
            xhi[p ^ 1][xb][xf] = h0; xlo[p ^ 1][xb][xf] = l0;
            int tn = (ts + 2 < T_SEQ) ? ts + 2 : T_SEQ - 1;
            xnext = x[(size_t)tn * NBATCH * NIN + (b0 + xb) * NIN + xf];
        }

        // ---- 4x4 butterfly transpose over gate bits (lane xor 4, xor 8) ----
        {
            float a0 = (G & 1) ? d0 : d1;
            float a1 = (G & 1) ? d2 : d3;
            a0 = __shfl_xor_sync(FULL, a0, 4);
            a1 = __shfl_xor_sync(FULL, a1, 4);
            if (G & 1) { d0 = a0; d2 = a1; } else { d1 = a0; d3 = a1; }
            float e0 = (G & 2) ? d0 : d2;
            float e1 = (G & 2) ? d1 : d3;
            e0 = __shfl_xor_sync(FULL, e0, 8);
            e1 = __shfl_xor_sync(FULL, e1, 8);
            if (G & 2) { d0 = e0; d1 = e1; } else { d2 = e0; d3 = e1; }
        }
        // now d0=zi, d1=zf, d2=zg, d3=zo for cell (jc, bc)

        float iv = siga(d0);
        float fv = siga(d1);
        float gv = tanha(d2);
        float ov = siga(d3);
        c = fmaf(fv, c, iv * gv);
        float h = ov * tanha(c);

        hsm[p ^ 1][bc][jc] = __float2half_rn(h);
        gptr[(size_t)ts * (NBATCH * NHEAD * HID)] = h;
        // loop-top barrier publishes buf p^1 for step ts+1
    }
}

// ============================================================================
// Epilogue: out[t,b,h] = dot(h, W_lin[h]) + b_lin[h]; lstm_out = sum over heads
// ============================================================================
__global__ __launch_bounds__(256) void lstm_epi_kernel(
    const float* __restrict__ W_lin,
    const float* __restrict__ b_lin,
    float* __restrict__ out,
    float* __restrict__ lstm_out)
{
    const int cell = blockIdx.x * 16 + (threadIdx.x >> 4);
    const int q    = threadIdx.x & 15;

    const float4* hist4 = reinterpret_cast<const float4*>(g_hist) + (size_t)cell * 128;
    float4 v[NHEAD];
#pragma unroll
    for (int h = 0; h < NHEAD; ++h) v[h] = hist4[h * 16 + q];

    float4 s = v[0];
#pragma unroll
    for (int h = 1; h < NHEAD; ++h) { s.x += v[h].x; s.y += v[h].y; s.z += v[h].z; s.w += v[h].w; }
    reinterpret_cast<float4*>(lstm_out)[(size_t)cell * 16 + q] = s;

    const float4* wl4 = reinterpret_cast<const float4*>(W_lin);
    float d[NHEAD];
#pragma unroll
    for (int h = 0; h < NHEAD; ++h) {
        float4 w = wl4[h * 16 + q];
        float acc = v[h].x * w.x;
        acc = fmaf(v[h].y, w.y, acc);
        acc = fmaf(v[h].z, w.z, acc);
        acc = fmaf(v[h].w, w.w, acc);
        d[h] = acc;
    }
#pragma unroll
    for (int off = 8; off > 0; off >>= 1) {
#pragma unroll
        for (int h = 0; h < NHEAD; ++h)
            d[h] += __shfl_xor_sync(0xFFFFFFFFu, d[h], off);
    }
    if (q == 0) {
#pragma unroll
        for (int h = 0; h < NHEAD; ++h)
            out[(size_t)cell * NHEAD + h] = d[h] + b_lin[h];
    }
}

extern "C" void kernel_launch(void* const* d_in, const int* in_sizes, int n_in,
                              void* d_out, int out_size) {
    const float* x     = (const float*)d_in[0];
    const float* W_ih  = (const float*)d_in[1];
    const float* W_hh  = (const float*)d_in[2];
    const float* b_ih  = (const float*)d_in[3];
    const float* b_hh  = (const float*)d_in[4];
    const float* W_lin = (const float*)d_in[5];
    const float* b_lin = (const float*)d_in[6];

    float* out      = (float*)d_out;                         // (T,B,H)
    float* lstm_out = out + (size_t)T_SEQ * NBATCH * NHEAD;  // (T,B,HID)

    lstm_rec_mma<<<NHEAD * (NBATCH / 8), 512>>>(x, W_ih, W_hh, b_ih, b_hh);
    lstm_epi_kernel<<<(T_SEQ * NBATCH) / 16, 256>>>(W_lin, b_lin, out, lstm_out);
}

// round 17
// speedup vs baseline: 2.2687x; 1.0624x over previous
#include <cuda_runtime.h>
#include <cuda_fp16.h>
#include <cstdint>

#define T_SEQ 2048
#define NBATCH 64
#define NIN 16
#define NHEAD 8
#define HID 64
#define NGATE 256

// h history scratch, fp16 (device global; no runtime allocation) — 128 MB
__device__ __half g_hist[(size_t)T_SEQ * NBATCH * NHEAD * HID];

// ---- helpers ----
__device__ __forceinline__ uint32_t pack_h2(__half a, __half b) {
    __half2 v; v.x = a; v.y = b;
    return *reinterpret_cast<uint32_t*>(&v);
}
__device__ __forceinline__ void mma16816(float& d0, float& d1, float& d2, float& d3,
                                         uint32_t a0, uint32_t a1, uint32_t a2, uint32_t a3,
                                         uint32_t b0, uint32_t b1) {
    asm volatile(
        "mma.sync.aligned.m16n8k16.row.col.f32.f16.f16.f32 "
        "{%0,%1,%2,%3},{%4,%5,%6,%7},{%8,%9},{%0,%1,%2,%3};"
        : "+f"(d0), "+f"(d1), "+f"(d2), "+f"(d3)
        : "r"(a0), "r"(a1), "r"(a2), "r"(a3), "r"(b0), "r"(b1));
}
__device__ __forceinline__ float tanha(float x) {
    float y; asm("tanh.approx.f32 %0, %1;" : "=f"(y) : "f"(x)); return y;
}
__device__ __forceinline__ float siga(float z) {          // 1 MUFU sigmoid
    return fmaf(0.5f, tanha(0.5f * z), 0.5f);
}
// swizzled half-index of hidden index k within a row: groups each lane's
// B-fragment quad {2tg, 2tg+1, 2tg+8, 2tg+9} (+16ks) contiguously.
__device__ __forceinline__ int hswz(int k) {
    return (k & 48) + (((k >> 1) & 3) << 2) + (((k >> 3) & 1) << 1) + (k & 1);
}

// ============================================================================
// Recurrent kernel, fp16 m16n8k16, gate-permuted tiles + register transpose.
// Grid: 64 CTAs = head(8) x batch-group(8). Block: 512 (16 warps).
// Warp w's m16 tile = 4 gates x 4 cells (permuted rows), so each warp owns
// all four gates of its cells; a 2-shuffle butterfly hands each lane
// (zi,zf,zg,zo) of one cell. ONE barrier per step.
// Step structure: [pre-barrier] d=bias, x-MMA (x single fp16, triple-buffered,
// published 2 steps ahead) -> [barrier] -> 4 LDS.64 (swizzled h) -> 4 h-MMAs
// in 2 independent chains -> combine -> transpose -> activation -> STS h
// (swizzled) + STG fp16 history.
// ============================================================================
__global__ __launch_bounds__(512, 1) void lstm_rec_mma(
    const float* __restrict__ x,     // (T,B,16)
    const float* __restrict__ W_ih,  // (8,256,16)
    const float* __restrict__ W_hh,  // (8,256,64)
    const float* __restrict__ b_ih,  // (8,256)
    const float* __restrict__ b_hh)  // (8,256)
{
    const int tid  = threadIdx.x;
    const int wid  = tid >> 5;
    const int lane = tid & 31;
    const int g    = lane >> 2;       // fragment group id
    const int tg   = lane & 3;
    const int G    = g & 3;           // gate of this lane's A rows
    const int q    = g >> 2;          // j-slot base (0 or 1)
    const int hd   = blockIdx.x >> 3;
    const int b0   = (blockIdx.x & 7) * 8;

    // my two A rows: (gate G, j0) and (gate G, j0+2)
    const int j0 = 4 * wid + q;
    const int rowA = G * 64 + j0;
    const int rowB = rowA + 2;

    // ---- A fragments (weights), single fp16x2, register resident ----
    uint32_t ah[4][4], ax[4];
    {
        const float* WhA = W_hh + ((size_t)hd * NGATE + rowA) * HID;
        const float* WhB = W_hh + ((size_t)hd * NGATE + rowB) * HID;
#pragma unroll
        for (int ks = 0; ks < 4; ++ks) {
#pragma unroll
            for (int r = 0; r < 4; ++r) {
                const float* Wr = (r & 1) ? WhB : WhA;
                int kk = 16 * ks + 2 * tg + (r >> 1) * 8;
                ah[ks][r] = pack_h2(__float2half_rn(Wr[kk]), __float2half_rn(Wr[kk + 1]));
            }
        }
        const float* WiA = W_ih + ((size_t)hd * NGATE + rowA) * NIN;
        const float* WiB = W_ih + ((size_t)hd * NGATE + rowB) * NIN;
#pragma unroll
        for (int r = 0; r < 4; ++r) {
            const float* Wr = (r & 1) ? WiB : WiA;
            int kk = 2 * tg + (r >> 1) * 8;
            ax[r] = pack_h2(__float2half_rn(Wr[kk]), __float2half_rn(Wr[kk + 1]));
        }
    }
    const float biasA = b_ih[hd * NGATE + rowA] + b_hh[hd * NGATE + rowA];
    const float biasB = b_ih[hd * NGATE + rowB] + b_hh[hd * NGATE + rowB];

    // my output cell after transpose
    const int jc = 4 * wid + q + 2 * (G >> 1);
    const int bc = 2 * tg + (G & 1);
    const int jsw = hswz(jc);                        // swizzled write index
    __half* gptr = g_hist + ((size_t)(b0 + bc) * NHEAD + hd) * HID + jc;

    // smem: double-buffered swizzled h (stride 80 halves), triple-buffered x
    __shared__ __align__(16) __half hsm[2][8][80];
    __shared__ __align__(16) __half xsm[3][8][24];

    for (int i = tid; i < 2 * 8 * 80; i += 512)
        (&hsm[0][0][0])[i] = __float2half(0.0f);

    // x loaders: 128 threads cover x[t, b0..b0+7, 0..15]; triple buffer:
    // slot ts%3 holds x(ts). Pre-fill slots 0,1; xnext holds x(2).
    float xnext = 0.0f;
    if (tid < 128) {
        int xb = tid >> 4, xf = tid & 15;
        xsm[0][xb][xf] = __float2half_rn(x[((size_t)b0 + xb) * NIN + xf]);
        xsm[1][xb][xf] = __float2half_rn(x[(size_t)NBATCH * NIN + (b0 + xb) * NIN + xf]);
        xnext = x[(size_t)2 * NBATCH * NIN + (b0 + xb) * NIN + xf];
    }
    __syncthreads();                 // publish initial hsm + xsm[0..1]

    float c = 0.0f;
    const unsigned FULL = 0xFFFFFFFFu;
    int s0 = 0;                      // slot of x(ts)

    for (int ts = 0; ts < T_SEQ; ++ts) {
        const int p = ts & 1;

        // ---- pre-barrier: bias seed + x-MMA (x(ts) published >=1 barrier ago)
        float d0 = biasA, d1 = biasA, d2 = biasB, d3 = biasB;
        {
            uint32_t bx0 = *reinterpret_cast<const uint32_t*>(&xsm[s0][g][2 * tg]);
            uint32_t bx1 = *reinterpret_cast<const uint32_t*>(&xsm[s0][g][2 * tg + 8]);
            mma16816(d0, d1, d2, d3, ax[0], ax[1], ax[2], ax[3], bx0, bx1);
        }

        __syncthreads();             // h(ts-1) in hsm[p], x(ts+1) slot visible

        // ---- recurrent: 4 swizzled LDS.64 + 4 h-MMAs in 2 chains
        float e0 = 0.0f, e1 = 0.0f, e2 = 0.0f, e3 = 0.0f;
        {
            const __half* hrow = &hsm[p][g][0];
            uint2 w0 = *reinterpret_cast<const uint2*>(hrow + 0 * 16 + tg * 4);
            uint2 w1 = *reinterpret_cast<const uint2*>(hrow + 1 * 16 + tg * 4);
            uint2 w2 = *reinterpret_cast<const uint2*>(hrow + 2 * 16 + tg * 4);
            uint2 w3 = *reinterpret_cast<const uint2*>(hrow + 3 * 16 + tg * 4);
            mma16816(d0, d1, d2, d3, ah[0][0], ah[0][1], ah[0][2], ah[0][3], w0.x, w0.y);
            mma16816(e0, e1, e2, e3, ah[1][0], ah[1][1], ah[1][2], ah[1][3], w1.x, w1.y);
            mma16816(d0, d1, d2, d3, ah[2][0], ah[2][1], ah[2][2], ah[2][3], w2.x, w2.y);
            mma16816(e0, e1, e2, e3, ah[3][0], ah[3][1], ah[3][2], ah[3][3], w3.x, w3.y);
        }

        // x loaders: publish x(ts+2) into slot (ts+2)%3, fetch x(ts+3)
        if (tid < 128) {
            int xb = tid >> 4, xf = tid & 15;
            int s2 = s0 + 2; if (s2 >= 3) s2 -= 3;
            xsm[s2][xb][xf] = __float2half_rn(xnext);
            int tn = (ts + 3 < T_SEQ) ? ts + 3 : T_SEQ - 1;
            xnext = x[(size_t)tn * NBATCH * NIN + (b0 + xb) * NIN + xf];
        }

        d0 += e0; d1 += e1; d2 += e2; d3 += e3;

        // ---- 4x4 butterfly transpose over gate bits (lane xor 4, xor 8) ----
        {
            float a0 = (G & 1) ? d0 : d1;
            float a1 = (G & 1) ? d2 : d3;
            a0 = __shfl_xor_sync(FULL, a0, 4);
            a1 = __shfl_xor_sync(FULL, a1, 4);
            if (G & 1) { d0 = a0; d2 = a1; } else { d1 = a0; d3 = a1; }
            float f0 = (G & 2) ? d0 : d2;
            float f1 = (G & 2) ? d1 : d3;
            f0 = __shfl_xor_sync(FULL, f0, 8);
            f1 = __shfl_xor_sync(FULL, f1, 8);
            if (G & 2) { d0 = f0; d1 = f1; } else { d2 = f0; d3 = f1; }
        }
        // d0=zi, d1=zf, d2=zg, d3=zo for cell (jc, bc)

        float iv = siga(d0);
        float fv = siga(d1);
        float gv = tanha(d2);
        float ov = siga(d3);
        c = fmaf(fv, c, iv * gv);
        float h = ov * tanha(c);

        __half h16 = __float2half_rn(h);
        hsm[p ^ 1][bc][jsw] = h16;
        gptr[(size_t)ts * (NBATCH * NHEAD * HID)] = h16;

        s0 += 1; if (s0 >= 3) s0 -= 3;
        // barrier at top of next iteration publishes hsm[p^1] / x slot
    }
}

// ============================================================================
// Epilogue (fp16 history): out[t,b,h] = dot(h, W_lin[h]) + b_lin[h];
// lstm_out[t,b,j] = sum_h h. 16 threads per (t,b) cell, 8B loads (coalesced).
// ============================================================================
__global__ __launch_bounds__(256) void lstm_epi_kernel(
    const float* __restrict__ W_lin,
    const float* __restrict__ b_lin,
    float* __restrict__ out,
    float* __restrict__ lstm_out)
{
    const int cell = blockIdx.x * 16 + (threadIdx.x >> 4);
    const int q    = threadIdx.x & 15;     // 4-wide j group

    const uint2* hist = reinterpret_cast<const uint2*>(g_hist) + (size_t)cell * 128;
    float4 v[NHEAD];
#pragma unroll
    for (int h = 0; h < NHEAD; ++h) {
        uint2 r = hist[h * 16 + q];
        __half2 lo = *reinterpret_cast<__half2*>(&r.x);
        __half2 hi = *reinterpret_cast<__half2*>(&r.y);
        float2 a = __half22float2(lo), b = __half22float2(hi);
        v[h] = make_float4(a.x, a.y, b.x, b.y);
    }

    float4 s = v[0];
#pragma unroll
    for (int h = 1; h < NHEAD; ++h) { s.x += v[h].x; s.y += v[h].y; s.z += v[h].z; s.w += v[h].w; }
    reinterpret_cast<float4*>(lstm_out)[(size_t)cell * 16 + q] = s;

    const float4* wl4 = reinterpret_cast<const float4*>(W_lin);
    float d[NHEAD];
#pragma unroll
    for (int h = 0; h < NHEAD; ++h) {
        float4 w = wl4[h * 16 + q];
        float acc = v[h].x * w.x;
        acc = fmaf(v[h].y, w.y, acc);
        acc = fmaf(v[h].z, w.z, acc);
        acc = fmaf(v[h].w, w.w, acc);
        d[h] = acc;
    }
#pragma unroll
    for (int off = 8; off > 0; off >>= 1) {
#pragma unroll
        for (int h = 0; h < NHEAD; ++h)
            d[h] += __shfl_xor_sync(0xFFFFFFFFu, d[h], off);
    }
    if (q == 0) {
#pragma unroll
        for (int h = 0; h < NHEAD; ++h)
            out[(size_t)cell * NHEAD + h] = d[h] + b_lin[h];
    }
}

extern "C" void kernel_launch(void* const* d_in, const int* in_sizes, int n_in,
                              void* d_out, int out_size) {
    const float* x     = (const float*)d_in[0];
    const float* W_ih  = (const float*)d_in[1];
    const float* W_hh  = (const float*)d_in[2];
    const float* b_ih  = (const float*)d_in[3];
    const float* b_hh  = (const float*)d_in[4];
    const float* W_lin = (const float*)d_in[5];
    const float* b_lin = (const float*)d_in[6];

    float* out      = (float*)d_out;                         // (T,B,H)
    float* lstm_out = out + (size_t)T_SEQ * NBATCH * NHEAD;  // (T,B,HID)

    lstm_rec_mma<<<NHEAD * (NBATCH / 8), 512>>>(x, W_ih, W_hh, b_ih, b_hh);
    lstm_epi_kernel<<<(T_SEQ * NBATCH) / 16, 256>>>(W_lin, b_lin, out, lstm_out);
}